// round 7
// baseline (speedup 1.0000x reference)
#include <cuda_runtime.h>
#include <cuda_bf16.h>
#include <math.h>
#include <stdint.h>

#define SQB 16384
#define SKK 4096
#define DDK 512
#define DVV 256

// ---------------- scratch ----------------
__device__ __align__(256) float  g_K[SKK * DDK];                 // projected K fp32
__device__ __align__(256) float  g_V[SKK * DVV];                 // projected V fp32
__device__ __align__(256) float  g_Vt[DVV * SKK];                // V^T fp32
__device__ __align__(256) float  g_S[(long long)SQB * SKK];      // scores fp32
__device__ __align__(256) int8_t g_Xd0[(long long)SQB * DDK];
__device__ __align__(256) int8_t g_Xd1[(long long)SQB * DDK];
__device__ __align__(256) int8_t g_Kd0[SKK * DDK];
__device__ __align__(256) int8_t g_Kd1[SKK * DDK];
__device__ __align__(256) int8_t g_Vtd0[DVV * SKK];
__device__ __align__(256) int8_t g_Vtd1[DVV * SKK];
__device__ __align__(256) int8_t g_Pd0[(long long)SQB * SKK];
__device__ __align__(256) int8_t g_Pd1[(long long)SQB * SKK];
__device__ __align__(256) float  g_sX[SQB];
__device__ __align__(256) float  g_sK[SKK];
__device__ __align__(256) float  g_sVt[DVV];
__device__ __align__(256) float  g_sP[SQB];

// ---------------- helpers ----------------
__device__ __forceinline__ uint32_t smem_u32(const void* p) {
    uint32_t a;
    asm("{ .reg .u64 t; cvta.to.shared.u64 t, %1; cvt.u32.u64 %0, t; }" : "=r"(a) : "l"(p));
    return a;
}
__device__ __forceinline__ void cp16(uint32_t s, const void* g) {
    asm volatile("cp.async.cg.shared.global [%0], [%1], 16;"
                 :: "r"(s), "l"(__cvta_generic_to_global(g)) : "memory");
}
#define CP_COMMIT() asm volatile("cp.async.commit_group;" ::: "memory")
#define CP_WAIT(n)  asm volatile("cp.async.wait_group %0;" :: "n"(n) : "memory")

#define LDSM4(r, a) \
    asm volatile("ldmatrix.sync.aligned.m8n8.x4.shared.b16 {%0,%1,%2,%3}, [%4];" \
                 : "=r"((r)[0]), "=r"((r)[1]), "=r"((r)[2]), "=r"((r)[3]) : "r"(a))

#define MMA_S8(d, a, b) \
    asm volatile("mma.sync.aligned.m16n8k32.row.col.s32.s8.s8.s32 " \
                 "{%0,%1,%2,%3}, {%4,%5,%6,%7}, {%8,%9}, {%0,%1,%2,%3};" \
                 : "+r"((d)[0]), "+r"((d)[1]), "+r"((d)[2]), "+r"((d)[3]) \
                 : "r"((a)[0]), "r"((a)[1]), "r"((a)[2]), "r"((a)[3]), \
                   "r"((b)[0]), "r"((b)[1]))

// ---------------- IMMA NT GEMM, 2-digit int8 split -----------------------
// C[M,N] = scale * sa[m] * sb[n] * ( acc0 + acc1/256 )
//   acc0 = A_d0 . B_d0^T ;  acc1 = A_d0 . B_d1^T + A_d1 . B_d0^T
// CTA 128x128, 256 thr (8 warps, 64x32 each). K-chunk 64 (two k32 MMAs).
#define KC 64
#define ROWB 80                 // 64B data + 16B pad (conflict-free, verified)
#define PLANE (128 * ROWB)      // 10240 B
#define OFF_AD0 0
#define OFF_AD1 (1 * PLANE)
#define OFF_BD0 (2 * PLANE)
#define OFF_BD1 (3 * PLANE)
#define STAGE  (4 * PLANE)      // 40960 B
#define SMEMSZ (2 * STAGE + 1024)

__device__ __forceinline__ void load_stage_i8(
    uint32_t base, int tid, int kc0, int Kdim,
    const int8_t* __restrict__ Ad0, const int8_t* __restrict__ Ad1,
    const int8_t* __restrict__ Bd0, const int8_t* __restrict__ Bd1,
    long long m0, long long n0)
{
#pragma unroll
    for (int it = 0; it < 2; it++) {
        const int j = tid + it * 256;        // 512 jobs: 128 rows x 4 x 16B
        const int row = j >> 2;
        const int part = j & 3;
        const uint32_t off = (uint32_t)row * ROWB + part * 16;
        const long long ga = (m0 + row) * (long long)Kdim + kc0 + part * 16;
        const long long gb = (n0 + row) * (long long)Kdim + kc0 + part * 16;
        cp16(base + OFF_AD0 + off, Ad0 + ga);
        cp16(base + OFF_AD1 + off, Ad1 + ga);
        cp16(base + OFF_BD0 + off, Bd0 + gb);
        cp16(base + OFF_BD1 + off, Bd1 + gb);
    }
    CP_COMMIT();
}

__global__ __launch_bounds__(256)
void imma_gemm_nt(const int8_t* __restrict__ Ad0, const int8_t* __restrict__ Ad1,
                  const int8_t* __restrict__ Bd0, const int8_t* __restrict__ Bd1,
                  const float* __restrict__ sa, const float* __restrict__ sb,
                  float* __restrict__ C, int Kdim, int ldc, float scale)
{
    extern __shared__ char sm[];
    const uint32_t sbse = smem_u32(sm);

    const int tid  = threadIdx.x;
    const int lane = tid & 31;
    const int wid  = tid >> 5;
    const int wm   = wid & 1;
    const int wn   = wid >> 1;
    const long long m0 = (long long)blockIdx.y * 128;
    const long long n0 = (long long)blockIdx.x * 128;

    // scale vectors -> smem
    float* sAs = (float*)(sm + 2 * STAGE);
    float* sBs = sAs + 128;
    if (tid < 128)       sAs[tid] = sa[m0 + tid];
    else                 sBs[tid - 128] = sb[n0 + tid - 128];

    int acc0[4][4][4], acc1[4][4][4];
#pragma unroll
    for (int i = 0; i < 4; i++)
#pragma unroll
        for (int j = 0; j < 4; j++)
#pragma unroll
            for (int k = 0; k < 4; k++) { acc0[i][j][k] = 0; acc1[i][j][k] = 0; }

    const int NC = Kdim / KC;
    load_stage_i8(sbse,         tid, 0,  Kdim, Ad0, Ad1, Bd0, Bd1, m0, n0);
    load_stage_i8(sbse + STAGE, tid, KC, Kdim, Ad0, Ad1, Bd0, Bd1, m0, n0);

    const int g = lane >> 3;
    const int r = lane & 7;

    for (int c = 0; c < NC; c++) {
        const int st = c & 1;
        const uint32_t base = sbse + st * STAGE;
        if (c + 2 < NC) { CP_WAIT(1); } else { CP_WAIT(0); }
        __syncthreads();

#pragma unroll
        for (int ks = 0; ks < 2; ks++) {
            uint32_t aD0[4][4], aD1[4][4], bD0[4][2], bD1[4][2];
            const uint32_t cb = ks * 32 + (g >> 1) * 16;
#pragma unroll
            for (int mi = 0; mi < 4; mi++) {
                const uint32_t row = wm * 64 + mi * 16 + (g & 1) * 8 + r;
                const uint32_t ad  = base + OFF_AD0 + row * ROWB + cb;
                LDSM4(aD0[mi], ad);
                LDSM4(aD1[mi], ad + (OFF_AD1 - OFF_AD0));
            }
#pragma unroll
            for (int np = 0; np < 2; np++) {
                const uint32_t row = wn * 32 + np * 16 + (g & 1) * 8 + r;
                const uint32_t bd  = base + OFF_BD0 + row * ROWB + cb;
                uint32_t t[4];
                LDSM4(t, bd);
                bD0[np * 2][0] = t[0]; bD0[np * 2][1] = t[2];
                bD0[np * 2 + 1][0] = t[1]; bD0[np * 2 + 1][1] = t[3];
                LDSM4(t, bd + (OFF_BD1 - OFF_BD0));
                bD1[np * 2][0] = t[0]; bD1[np * 2][1] = t[2];
                bD1[np * 2 + 1][0] = t[1]; bD1[np * 2 + 1][1] = t[3];
            }
            // term-outermost ordering (16 independent MMAs between same-acc writes)
#pragma unroll
            for (int mi = 0; mi < 4; mi++)
#pragma unroll
                for (int ni = 0; ni < 4; ni++)
                    MMA_S8(acc0[mi][ni], aD0[mi], bD0[ni]);
#pragma unroll
            for (int mi = 0; mi < 4; mi++)
#pragma unroll
                for (int ni = 0; ni < 4; ni++)
                    MMA_S8(acc1[mi][ni], aD0[mi], bD1[ni]);
#pragma unroll
            for (int mi = 0; mi < 4; mi++)
#pragma unroll
                for (int ni = 0; ni < 4; ni++)
                    MMA_S8(acc1[mi][ni], aD1[mi], bD0[ni]);
        }
        __syncthreads();
        if (c + 2 < NC)
            load_stage_i8(base, tid, (c + 2) * KC, Kdim, Ad0, Ad1, Bd0, Bd1, m0, n0);
    }

    // epilogue
#pragma unroll
    for (int mi = 0; mi < 4; mi++)
#pragma unroll
        for (int ni = 0; ni < 4; ni++) {
            const int rr = wm * 64 + mi * 16 + (lane >> 2);
            const int cc = wn * 32 + ni * 8 + 2 * (lane & 3);
            const float fa0 = sAs[rr] * scale, fa1 = sAs[rr + 8] * scale;
            const float fb0 = sBs[cc], fb1 = sBs[cc + 1];
            const float q = 1.0f / 256.0f;
            float v00 = ((float)acc0[mi][ni][0] + (float)acc1[mi][ni][0] * q) * fa0 * fb0;
            float v01 = ((float)acc0[mi][ni][1] + (float)acc1[mi][ni][1] * q) * fa0 * fb1;
            float v10 = ((float)acc0[mi][ni][2] + (float)acc1[mi][ni][2] * q) * fa1 * fb0;
            float v11 = ((float)acc0[mi][ni][3] + (float)acc1[mi][ni][3] * q) * fa1 * fb1;
            const long long row = m0 + rr;
            const long long col = n0 + cc;
            *(float2*)&C[row * ldc + col]       = make_float2(v00, v01);
            *(float2*)&C[(row + 8) * ldc + col] = make_float2(v10, v11);
        }
}

// ---------------- fp32 NT SGEMM for projections ----------------
#define BM 128
#define BN 128
#define BKK 8
#define PADW 132

__global__ __launch_bounds__(256, 2)
void sgemm_nt(const float* __restrict__ Ag, const float* __restrict__ Bg,
              float* __restrict__ Cg, int N, int K)
{
    __shared__ float As[2][BKK][PADW];
    __shared__ float Bs[2][BKK][PADW];

    const int tid = threadIdx.x;
    const int tx = tid & 15, ty = tid >> 4;
    const int row0 = blockIdx.y * BM, col0 = blockIdx.x * BN;
    const int aRow = row0 + (tid >> 1);
    const int aCol = (tid & 1) * 4;
    const int bRow = col0 + (tid >> 1);

    float acc[8][8];
#pragma unroll
    for (int i = 0; i < 8; i++)
#pragma unroll
        for (int j = 0; j < 8; j++) acc[i][j] = 0.f;

    const int nt = K / BKK;
    float4 ra = *(const float4*)&Ag[(long long)aRow * K + aCol];
    float4 rb = *(const float4*)&Bg[(long long)bRow * K + aCol];
    {
        const int m = tid >> 1;
        As[0][aCol + 0][m] = ra.x; As[0][aCol + 1][m] = ra.y;
        As[0][aCol + 2][m] = ra.z; As[0][aCol + 3][m] = ra.w;
        Bs[0][aCol + 0][m] = rb.x; Bs[0][aCol + 1][m] = rb.y;
        Bs[0][aCol + 2][m] = rb.z; Bs[0][aCol + 3][m] = rb.w;
    }
    __syncthreads();

    for (int t = 0; t < nt; t++) {
        const int buf = t & 1;
        if (t + 1 < nt) {
            const int k0 = (t + 1) * BKK;
            ra = *(const float4*)&Ag[(long long)aRow * K + k0 + aCol];
            rb = *(const float4*)&Bg[(long long)bRow * K + k0 + aCol];
        }
#pragma unroll
        for (int kk = 0; kk < BKK; kk++) {
            float4 a0 = *(const float4*)&As[buf][kk][ty * 4];
            float4 a1 = *(const float4*)&As[buf][kk][64 + ty * 4];
            float4 b0 = *(const float4*)&Bs[buf][kk][tx * 4];
            float4 b1 = *(const float4*)&Bs[buf][kk][64 + tx * 4];
            float av[8] = {a0.x, a0.y, a0.z, a0.w, a1.x, a1.y, a1.z, a1.w};
            float bv[8] = {b0.x, b0.y, b0.z, b0.w, b1.x, b1.y, b1.z, b1.w};
#pragma unroll
            for (int i = 0; i < 8; i++)
#pragma unroll
                for (int j = 0; j < 8; j++)
                    acc[i][j] += av[i] * bv[j];
        }
        if (t + 1 < nt) {
            const int nb = (t + 1) & 1;
            const int m = tid >> 1;
            As[nb][aCol + 0][m] = ra.x; As[nb][aCol + 1][m] = ra.y;
            As[nb][aCol + 2][m] = ra.z; As[nb][aCol + 3][m] = ra.w;
            Bs[nb][aCol + 0][m] = rb.x; Bs[nb][aCol + 1][m] = rb.y;
            Bs[nb][aCol + 2][m] = rb.z; Bs[nb][aCol + 3][m] = rb.w;
        }
        __syncthreads();
    }

#pragma unroll
    for (int i = 0; i < 8; i++) {
        const int r = row0 + ((i < 4) ? (ty * 4 + i) : (64 + ty * 4 + (i - 4)));
        float4 v0 = make_float4(acc[i][0], acc[i][1], acc[i][2], acc[i][3]);
        float4 v1 = make_float4(acc[i][4], acc[i][5], acc[i][6], acc[i][7]);
        *(float4*)&Cg[(long long)r * N + col0 + tx * 4]      = v0;
        *(float4*)&Cg[(long long)r * N + col0 + 64 + tx * 4] = v1;
    }
}

// ---------------- quantization helpers ----------------
__device__ __forceinline__ uint32_t pack4_s8(float q0, float q1, float q2, float q3) {
    return ((uint32_t)(uint8_t)(int8_t)(int)q0)
         | ((uint32_t)(uint8_t)(int8_t)(int)q1 << 8)
         | ((uint32_t)(uint8_t)(int8_t)(int)q2 << 16)
         | ((uint32_t)(uint8_t)(int8_t)(int)q3 << 24);
}

// Per-row 2-digit int8 quantization: x ~= s*(d0 + d1/256), s = max|x|/127.
__global__ __launch_bounds__(256)
void quant_rows(const float* __restrict__ in, int8_t* __restrict__ d0,
                int8_t* __restrict__ d1, float* __restrict__ sc, int L)
{
    const long long base = (long long)blockIdx.x * L;
    const int tid = threadIdx.x, lane = tid & 31, wid = tid >> 5;

    float mx = 0.f;
    for (int i = tid * 4; i < L; i += 1024) {
        float4 v = *(const float4*)&in[base + i];
        mx = fmaxf(mx, fmaxf(fmaxf(fabsf(v.x), fabsf(v.y)),
                             fmaxf(fabsf(v.z), fabsf(v.w))));
    }
#pragma unroll
    for (int o = 16; o > 0; o >>= 1) mx = fmaxf(mx, __shfl_xor_sync(0xffffffffu, mx, o));
    __shared__ float red[8];
    if (lane == 0) red[wid] = mx;
    __syncthreads();
    mx = red[0];
#pragma unroll
    for (int i = 1; i < 8; i++) mx = fmaxf(mx, red[i]);

    const float s    = mx * (1.0f / 127.0f);
    const float invs = (mx > 0.f) ? 127.0f / mx : 0.f;
    if (tid == 0) sc[blockIdx.x] = s;

    for (int i = tid * 4; i < L; i += 1024) {
        float4 v = *(const float4*)&in[base + i];
        float t0 = v.x * invs, t1 = v.y * invs, t2 = v.z * invs, t3 = v.w * invs;
        float q0 = rintf(t0), q1 = rintf(t1), q2 = rintf(t2), q3 = rintf(t3);
        float e0 = fminf(fmaxf(256.f * (t0 - q0), -127.f), 127.f);
        float e1 = fminf(fmaxf(256.f * (t1 - q1), -127.f), 127.f);
        float e2 = fminf(fmaxf(256.f * (t2 - q2), -127.f), 127.f);
        float e3 = fminf(fmaxf(256.f * (t3 - q3), -127.f), 127.f);
        *(uint32_t*)&d0[base + i] = pack4_s8(q0, q1, q2, q3);
        *(uint32_t*)&d1[base + i] = pack4_s8(rintf(e0), rintf(e1), rintf(e2), rintf(e3));
    }
}

// V [4096,256] fp32 -> Vt [256,4096] fp32 (32x32 smem tiles)
__global__ __launch_bounds__(256)
void transpose_v(const float* __restrict__ V, float* __restrict__ Vt)
{
    __shared__ float t[32][33];
    const int x = threadIdx.x & 31;
    const int y = threadIdx.x >> 5;
    const int k0 = blockIdx.x * 32;
    const int n0 = blockIdx.y * 32;
#pragma unroll
    for (int i = 0; i < 4; i++)
        t[y + i * 8][x] = V[(long long)(k0 + y + i * 8) * 256 + n0 + x];
    __syncthreads();
#pragma unroll
    for (int i = 0; i < 4; i++)
        Vt[(long long)(n0 + y + i * 8) * 4096 + k0 + x] = t[x][y + i * 8];
}

// ---------------- softmax (fp32 in) -> P digits + scale ----------------
__global__ __launch_bounds__(256)
void softmax_quant_kernel(const float* __restrict__ S,
                          int8_t* __restrict__ Pd0, int8_t* __restrict__ Pd1,
                          float* __restrict__ sP)
{
    const long long rbase = (long long)blockIdx.x * 4096;
    const float* p = S + rbase;
    const int tid = threadIdx.x, wid = tid >> 5, lane = tid & 31;

    float4 v[4];
#pragma unroll
    for (int i = 0; i < 4; i++) v[i] = *(const float4*)&p[i * 1024 + tid * 4];

    float m = -INFINITY;
#pragma unroll
    for (int i = 0; i < 4; i++)
        m = fmaxf(m, fmaxf(fmaxf(v[i].x, v[i].y), fmaxf(v[i].z, v[i].w)));
#pragma unroll
    for (int o = 16; o > 0; o >>= 1) m = fmaxf(m, __shfl_xor_sync(0xffffffffu, m, o));

    __shared__ float redm[8], reds[8];
    if (lane == 0) redm[wid] = m;
    __syncthreads();
    m = redm[0];
#pragma unroll
    for (int i = 1; i < 8; i++) m = fmaxf(m, redm[i]);

    float s = 0.f;
#pragma unroll
    for (int i = 0; i < 4; i++) {
        v[i].x = __expf(v[i].x - m); v[i].y = __expf(v[i].y - m);
        v[i].z = __expf(v[i].z - m); v[i].w = __expf(v[i].w - m);
        s += v[i].x + v[i].y + v[i].z + v[i].w;
    }
#pragma unroll
    for (int o = 16; o > 0; o >>= 1) s += __shfl_xor_sync(0xffffffffu, s, o);
    if (lane == 0) reds[wid] = s;
    __syncthreads();
    s = 0.f;
#pragma unroll
    for (int i = 0; i < 8; i++) s += reds[i];
    const float inv = 1.0f / s;

    // P = e * inv; scale = inv/127 (row max of P is exactly inv). d0 = rint(127*e).
    if (tid == 0) sP[blockIdx.x] = inv * (1.0f / 127.0f);

#pragma unroll
    for (int i = 0; i < 4; i++) {
        float t0 = 127.f * v[i].x, t1 = 127.f * v[i].y;
        float t2 = 127.f * v[i].z, t3 = 127.f * v[i].w;
        float q0 = rintf(t0), q1 = rintf(t1), q2 = rintf(t2), q3 = rintf(t3);
        float e0 = fminf(fmaxf(256.f * (t0 - q0), -127.f), 127.f);
        float e1 = fminf(fmaxf(256.f * (t1 - q1), -127.f), 127.f);
        float e2 = fminf(fmaxf(256.f * (t2 - q2), -127.f), 127.f);
        float e3 = fminf(fmaxf(256.f * (t3 - q3), -127.f), 127.f);
        const long long off = rbase + i * 1024 + tid * 4;
        *(uint32_t*)&Pd0[off] = pack4_s8(q0, q1, q2, q3);
        *(uint32_t*)&Pd1[off] = pack4_s8(rintf(e0), rintf(e1), rintf(e2), rintf(e3));
    }
}

// ---------------------------------------------------------------------------
extern "C" void kernel_launch(void* const* d_in, const int* in_sizes, int n_in,
                              void* d_out, int out_size)
{
    (void)in_sizes; (void)n_in; (void)out_size;
    const float* X  = (const float*)d_in[0];
    const float* Y  = (const float*)d_in[1];
    const float* Z  = (const float*)d_in[2];
    const float* Wk = (const float*)d_in[3];
    const float* Wv = (const float*)d_in[4];
    float* out = (float*)d_out;

    float *Kp, *Vp, *Vtp, *Sp, *sX, *sK, *sVt, *sP;
    int8_t *Xd0, *Xd1, *Kd0, *Kd1, *Vtd0, *Vtd1, *Pd0, *Pd1;
    cudaGetSymbolAddress((void**)&Kp,   g_K);
    cudaGetSymbolAddress((void**)&Vp,   g_V);
    cudaGetSymbolAddress((void**)&Vtp,  g_Vt);
    cudaGetSymbolAddress((void**)&Sp,   g_S);
    cudaGetSymbolAddress((void**)&Xd0,  g_Xd0);
    cudaGetSymbolAddress((void**)&Xd1,  g_Xd1);
    cudaGetSymbolAddress((void**)&Kd0,  g_Kd0);
    cudaGetSymbolAddress((void**)&Kd1,  g_Kd1);
    cudaGetSymbolAddress((void**)&Vtd0, g_Vtd0);
    cudaGetSymbolAddress((void**)&Vtd1, g_Vtd1);
    cudaGetSymbolAddress((void**)&Pd0,  g_Pd0);
    cudaGetSymbolAddress((void**)&Pd1,  g_Pd1);
    cudaGetSymbolAddress((void**)&sX,   g_sX);
    cudaGetSymbolAddress((void**)&sK,   g_sK);
    cudaGetSymbolAddress((void**)&sVt,  g_sVt);
    cudaGetSymbolAddress((void**)&sP,   g_sP);

    cudaFuncSetAttribute(imma_gemm_nt, cudaFuncAttributeMaxDynamicSharedMemorySize, SMEMSZ);

    const float rs = 0.0441941738241592f;  // 1/sqrt(512)

    // Projections (fp32 FFMA)
    sgemm_nt<<<dim3(512 / BN, 4096 / BM), 256>>>(Y, Wk, Kp, 512, 512);
    sgemm_nt<<<dim3(256 / BN, 4096 / BM), 256>>>(Z, Wv, Vp, 256, 512);

    // quantize operands (per-row 2-digit int8)
    quant_rows<<<SQB, 256>>>(X, Xd0, Xd1, sX, DDK);
    quant_rows<<<SKK, 256>>>(Kp, Kd0, Kd1, sK, DDK);
    transpose_v<<<dim3(SKK / 32, DVV / 32), 256>>>(Vp, Vtp);
    quant_rows<<<DVV, 256>>>(Vtp, Vtd0, Vtd1, sVt, SKK);

    // S = X K^T * rs  (IMMA 2-digit)
    imma_gemm_nt<<<dim3(SKK / 128, SQB / 128), 256, SMEMSZ>>>(
        Xd0, Xd1, Kd0, Kd1, sX, sK, Sp, DDK, SKK, rs);

    // softmax + P quantization (scale known in closed form)
    softmax_quant_kernel<<<SQB, 256>>>(Sp, Pd0, Pd1, sP);

    // out = P V  (IMMA 2-digit)
    imma_gemm_nt<<<dim3(DVV / 128, SQB / 128), 256, SMEMSZ>>>(
        Pd0, Pd1, Vtd0, Vtd1, sP, sVt, out, SKK, DVV, 1.f);
}

// round 8
// speedup vs baseline: 3.2969x; 3.2969x over previous
#include <cuda_runtime.h>
#include <cuda_fp16.h>
#include <math.h>
#include <stdint.h>

#define SQB 16384
#define SKK 4096
#define DDK 512
#define DVV 256

// ---------------- scratch ----------------
__device__ __align__(256) float  g_K[SKK * DDK];
__device__ __align__(256) float  g_V[SKK * DVV];
__device__ __align__(256) float  g_S[(long long)SQB * SKK];
__device__ __align__(256) __half g_Xh[(long long)SQB * DDK];
__device__ __align__(256) __half g_Kh[SKK * DDK];
__device__ __align__(256) __half g_Kl[SKK * DDK];
__device__ __align__(256) __half g_Vth[DVV * SKK];
__device__ __align__(256) __half g_Vtl[DVV * SKK];
__device__ __align__(256) __half g_Ph[(long long)SQB * SKK];

// ---------------- helpers ----------------
__device__ __forceinline__ uint32_t smem_u32(const void* p) {
    uint32_t a;
    asm("{ .reg .u64 t; cvta.to.shared.u64 t, %1; cvt.u32.u64 %0, t; }" : "=r"(a) : "l"(p));
    return a;
}
__device__ __forceinline__ void cp16(uint32_t s, const void* g) {
    asm volatile("cp.async.cg.shared.global [%0], [%1], 16;"
                 :: "r"(s), "l"(__cvta_generic_to_global(g)) : "memory");
}
#define CP_COMMIT() asm volatile("cp.async.commit_group;" ::: "memory")
#define CP_WAIT(n)  asm volatile("cp.async.wait_group %0;" :: "n"(n) : "memory")

#define LDSM4(r, a) \
    asm volatile("ldmatrix.sync.aligned.m8n8.x4.shared.b16 {%0,%1,%2,%3}, [%4];" \
                 : "=r"((r)[0]), "=r"((r)[1]), "=r"((r)[2]), "=r"((r)[3]) : "r"(a))

#define MMA_F16(d, a, b) \
    asm volatile("mma.sync.aligned.m16n8k16.row.col.f32.f16.f16.f32 " \
                 "{%0,%1,%2,%3}, {%4,%5,%6,%7}, {%8,%9}, {%0,%1,%2,%3};" \
                 : "+f"((d)[0]), "+f"((d)[1]), "+f"((d)[2]), "+f"((d)[3]) \
                 : "r"((a)[0]), "r"((a)[1]), "r"((a)[2]), "r"((a)[3]), \
                   "r"((b)[0]), "r"((b)[1]))

// ---------------- HMMA NT GEMM, asymmetric fp16 2-digit split --------------
// C[M,N] = A[M,K] * (Bh+Bl)[N,K]^T * scale   (A single fp16, B exact to 2^-22)
// CTA 128x128, 256 thr (8 warps, 64x32 each). K-chunk 32, 2 stages.
#define KC 32
#define ROWB 80                 // 64B data + 16B pad per smem row
#define PLANE (128 * ROWB)      // 10240 B
#define OFF_A  0
#define OFF_BH (1 * PLANE)
#define OFF_BL (2 * PLANE)
#define STAGE  (3 * PLANE)      // 30720 B
#define SMEMSZ (2 * STAGE)      // 61440 B

__device__ __forceinline__ void load_stage(
    uint32_t base, int tid, int kc0, int Kdim,
    const __half* __restrict__ A,
    const __half* __restrict__ Bh, const __half* __restrict__ Bl,
    long long m0, long long n0)
{
#pragma unroll
    for (int it = 0; it < 2; it++) {
        const int j = tid + it * 256;        // 512 jobs: 128 rows x 4 x 16B
        const int row = j >> 2;
        const int part = j & 3;
        const uint32_t off = (uint32_t)row * ROWB + part * 16;
        const long long ga = (m0 + row) * (long long)Kdim + kc0 + part * 8;
        const long long gb = (n0 + row) * (long long)Kdim + kc0 + part * 8;
        cp16(base + OFF_A  + off, A  + ga);
        cp16(base + OFF_BH + off, Bh + gb);
        cp16(base + OFF_BL + off, Bl + gb);
    }
    CP_COMMIT();
}

__global__ __launch_bounds__(256)
void hmma_gemm_nt(const __half* __restrict__ A,
                  const __half* __restrict__ Bh, const __half* __restrict__ Bl,
                  float* __restrict__ C, int Kdim, int ldc, float scale)
{
    extern __shared__ char sm[];
    const uint32_t sb = smem_u32(sm);

    const int tid  = threadIdx.x;
    const int lane = tid & 31;
    const int wid  = tid >> 5;
    const int wm   = wid & 1;    // 2 warps along M
    const int wn   = wid >> 1;   // 4 warps along N
    const long long m0 = (long long)blockIdx.y * 128;
    const long long n0 = (long long)blockIdx.x * 128;

    float acc[4][4][4];
#pragma unroll
    for (int i = 0; i < 4; i++)
#pragma unroll
        for (int j = 0; j < 4; j++)
#pragma unroll
            for (int k = 0; k < 4; k++) acc[i][j][k] = 0.f;

    const int NC = Kdim / KC;

    load_stage(sb,         tid, 0,  Kdim, A, Bh, Bl, m0, n0);
    load_stage(sb + STAGE, tid, KC, Kdim, A, Bh, Bl, m0, n0);

    const int g = lane >> 3;
    const int r = lane & 7;

    for (int c = 0; c < NC; c++) {
        const int st = c & 1;
        const uint32_t base = sb + st * STAGE;
        if (c + 2 < NC) { CP_WAIT(1); } else { CP_WAIT(0); }
        __syncthreads();

#pragma unroll
        for (int ks = 0; ks < 2; ks++) {
            uint32_t a_f[4][4], b_h[4][2], b_l[4][2];
            // A fragments: 4 m16 tiles (single plane)
#pragma unroll
            for (int mi = 0; mi < 4; mi++) {
                const uint32_t row = wm * 64 + mi * 16 + (g & 1) * 8 + r;
                const uint32_t cb  = ks * 32 + (g >> 1) * 16;
                LDSM4(a_f[mi], base + OFF_A + row * ROWB + cb);
            }
            // B fragments: 4 n8 tiles as 2 pairs, hi + lo planes
#pragma unroll
            for (int np = 0; np < 2; np++) {
                const uint32_t row = wn * 32 + np * 16 + (g >> 1) * 8 + r;
                const uint32_t cb  = ks * 32 + (g & 1) * 16;
                const uint32_t bd  = base + OFF_BH + row * ROWB + cb;
                uint32_t t[4];
                LDSM4(t, bd);
                b_h[np * 2][0] = t[0]; b_h[np * 2][1] = t[1];
                b_h[np * 2 + 1][0] = t[2]; b_h[np * 2 + 1][1] = t[3];
                LDSM4(t, bd + (OFF_BL - OFF_BH));
                b_l[np * 2][0] = t[0]; b_l[np * 2][1] = t[1];
                b_l[np * 2 + 1][0] = t[2]; b_l[np * 2 + 1][1] = t[3];
            }
            // 2-term split, term OUTERMOST (16 independent MMAs between
            // same-accumulator writes)
#pragma unroll
            for (int mi = 0; mi < 4; mi++)
#pragma unroll
                for (int ni = 0; ni < 4; ni++)
                    MMA_F16(acc[mi][ni], a_f[mi], b_h[ni]);
#pragma unroll
            for (int mi = 0; mi < 4; mi++)
#pragma unroll
                for (int ni = 0; ni < 4; ni++)
                    MMA_F16(acc[mi][ni], a_f[mi], b_l[ni]);
        }
        __syncthreads();
        if (c + 2 < NC)
            load_stage(base, tid, (c + 2) * KC, Kdim, A, Bh, Bl, m0, n0);
    }

    // epilogue: fragment -> gmem (float2 stores)
#pragma unroll
    for (int mi = 0; mi < 4; mi++)
#pragma unroll
        for (int ni = 0; ni < 4; ni++) {
            const long long row = m0 + wm * 64 + mi * 16 + (lane >> 2);
            const long long col = n0 + wn * 32 + ni * 8 + 2 * (lane & 3);
            float2 v0 = make_float2(acc[mi][ni][0] * scale, acc[mi][ni][1] * scale);
            float2 v1 = make_float2(acc[mi][ni][2] * scale, acc[mi][ni][3] * scale);
            *(float2*)&C[row * ldc + col]       = v0;
            *(float2*)&C[(row + 8) * ldc + col] = v1;
        }
}

// ---------------- fp32 NT SGEMM for projections ----------------
#define BM 128
#define BN 128
#define BKK 8
#define PADW 132

__global__ __launch_bounds__(256, 2)
void sgemm_nt(const float* __restrict__ Ag, const float* __restrict__ Bg,
              float* __restrict__ Cg, int N, int K)
{
    __shared__ float As[2][BKK][PADW];
    __shared__ float Bs[2][BKK][PADW];

    const int tid = threadIdx.x;
    const int tx = tid & 15, ty = tid >> 4;
    const int row0 = blockIdx.y * BM, col0 = blockIdx.x * BN;
    const int aRow = row0 + (tid >> 1);
    const int aCol = (tid & 1) * 4;
    const int bRow = col0 + (tid >> 1);

    float acc[8][8];
#pragma unroll
    for (int i = 0; i < 8; i++)
#pragma unroll
        for (int j = 0; j < 8; j++) acc[i][j] = 0.f;

    const int nt = K / BKK;
    float4 ra = *(const float4*)&Ag[(long long)aRow * K + aCol];
    float4 rb = *(const float4*)&Bg[(long long)bRow * K + aCol];
    {
        const int m = tid >> 1;
        As[0][aCol + 0][m] = ra.x; As[0][aCol + 1][m] = ra.y;
        As[0][aCol + 2][m] = ra.z; As[0][aCol + 3][m] = ra.w;
        Bs[0][aCol + 0][m] = rb.x; Bs[0][aCol + 1][m] = rb.y;
        Bs[0][aCol + 2][m] = rb.z; Bs[0][aCol + 3][m] = rb.w;
    }
    __syncthreads();

    for (int t = 0; t < nt; t++) {
        const int buf = t & 1;
        if (t + 1 < nt) {
            const int k0 = (t + 1) * BKK;
            ra = *(const float4*)&Ag[(long long)aRow * K + k0 + aCol];
            rb = *(const float4*)&Bg[(long long)bRow * K + k0 + aCol];
        }
#pragma unroll
        for (int kk = 0; kk < BKK; kk++) {
            float4 a0 = *(const float4*)&As[buf][kk][ty * 4];
            float4 a1 = *(const float4*)&As[buf][kk][64 + ty * 4];
            float4 b0 = *(const float4*)&Bs[buf][kk][tx * 4];
            float4 b1 = *(const float4*)&Bs[buf][kk][64 + tx * 4];
            float av[8] = {a0.x, a0.y, a0.z, a0.w, a1.x, a1.y, a1.z, a1.w};
            float bv[8] = {b0.x, b0.y, b0.z, b0.w, b1.x, b1.y, b1.z, b1.w};
#pragma unroll
            for (int i = 0; i < 8; i++)
#pragma unroll
                for (int j = 0; j < 8; j++)
                    acc[i][j] += av[i] * bv[j];
        }
        if (t + 1 < nt) {
            const int nb = (t + 1) & 1;
            const int m = tid >> 1;
            As[nb][aCol + 0][m] = ra.x; As[nb][aCol + 1][m] = ra.y;
            As[nb][aCol + 2][m] = ra.z; As[nb][aCol + 3][m] = ra.w;
            Bs[nb][aCol + 0][m] = rb.x; Bs[nb][aCol + 1][m] = rb.y;
            Bs[nb][aCol + 2][m] = rb.z; Bs[nb][aCol + 3][m] = rb.w;
        }
        __syncthreads();
    }

#pragma unroll
    for (int i = 0; i < 8; i++) {
        const int r = row0 + ((i < 4) ? (ty * 4 + i) : (64 + ty * 4 + (i - 4)));
        float4 v0 = make_float4(acc[i][0], acc[i][1], acc[i][2], acc[i][3]);
        float4 v1 = make_float4(acc[i][4], acc[i][5], acc[i][6], acc[i][7]);
        *(float4*)&Cg[(long long)r * N + col0 + tx * 4]      = v0;
        *(float4*)&Cg[(long long)r * N + col0 + 64 + tx * 4] = v1;
    }
}

// ---------------- conversion kernels ----------------
__device__ __forceinline__ uint32_t packh2(__half a, __half b) {
    return (uint32_t)__half_as_ushort(a) | ((uint32_t)__half_as_ushort(b) << 16);
}

// fp32 -> fp16 (single digit), 4 elems/thread
__global__ __launch_bounds__(256)
void tohalf_kernel(const float* __restrict__ in, __half* __restrict__ out)
{
    const long long i = (long long)blockIdx.x * 256 + threadIdx.x;
    float4 v = ((const float4*)in)[i];
    ((uint2*)out)[i] = make_uint2(packh2(__float2half_rn(v.x), __float2half_rn(v.y)),
                                  packh2(__float2half_rn(v.z), __float2half_rn(v.w)));
}

// fp32 -> fp16 hi/lo 2-digit
__global__ __launch_bounds__(256)
void split2_kernel(const float* __restrict__ in, __half* __restrict__ hi,
                   __half* __restrict__ lo)
{
    const long long i = (long long)blockIdx.x * 256 + threadIdx.x;
    float4 v = ((const float4*)in)[i];
    __half h0 = __float2half_rn(v.x), h1 = __float2half_rn(v.y);
    __half h2 = __float2half_rn(v.z), h3 = __float2half_rn(v.w);
    __half l0 = __float2half_rn(v.x - __half2float(h0));
    __half l1 = __float2half_rn(v.y - __half2float(h1));
    __half l2 = __float2half_rn(v.z - __half2float(h2));
    __half l3 = __float2half_rn(v.w - __half2float(h3));
    ((uint2*)hi)[i] = make_uint2(packh2(h0, h1), packh2(h2, h3));
    ((uint2*)lo)[i] = make_uint2(packh2(l0, l1), packh2(l2, l3));
}

// V [4096,256] fp32 -> V^T [256,4096] fp16 hi/lo, 32x32 smem tile transpose
__global__ __launch_bounds__(256)
void vtsplit_kernel(const float* __restrict__ V,
                    __half* __restrict__ th, __half* __restrict__ tl)
{
    __shared__ float t[32][33];
    const int x = threadIdx.x & 31;
    const int y = threadIdx.x >> 5;
    const int k0 = blockIdx.x * 32;
    const int n0 = blockIdx.y * 32;
#pragma unroll
    for (int i = 0; i < 4; i++)
        t[y + i * 8][x] = V[(long long)(k0 + y + i * 8) * 256 + n0 + x];
    __syncthreads();
#pragma unroll
    for (int i = 0; i < 4; i++) {
        const float v = t[x][y + i * 8];
        const __half h = __float2half_rn(v);
        const long long o = (long long)(n0 + y + i * 8) * 4096 + k0 + x;
        th[o] = h;
        tl[o] = __float2half_rn(v - __half2float(h));
    }
}

// ---------------- softmax (fp32 in) -> P fp16 ----------------
__global__ __launch_bounds__(256)
void softmax_half_kernel(const float* __restrict__ S, __half* __restrict__ Ph)
{
    const long long rbase = (long long)blockIdx.x * 4096;
    const float* p = S + rbase;
    const int tid = threadIdx.x, wid = tid >> 5, lane = tid & 31;

    float4 v[4];
#pragma unroll
    for (int i = 0; i < 4; i++) v[i] = *(const float4*)&p[i * 1024 + tid * 4];

    float m = -INFINITY;
#pragma unroll
    for (int i = 0; i < 4; i++)
        m = fmaxf(m, fmaxf(fmaxf(v[i].x, v[i].y), fmaxf(v[i].z, v[i].w)));
#pragma unroll
    for (int o = 16; o > 0; o >>= 1) m = fmaxf(m, __shfl_xor_sync(0xffffffffu, m, o));

    __shared__ float redm[8], reds[8];
    if (lane == 0) redm[wid] = m;
    __syncthreads();
    m = redm[0];
#pragma unroll
    for (int i = 1; i < 8; i++) m = fmaxf(m, redm[i]);

    float s = 0.f;
#pragma unroll
    for (int i = 0; i < 4; i++) {
        v[i].x = __expf(v[i].x - m); v[i].y = __expf(v[i].y - m);
        v[i].z = __expf(v[i].z - m); v[i].w = __expf(v[i].w - m);
        s += v[i].x + v[i].y + v[i].z + v[i].w;
    }
#pragma unroll
    for (int o = 16; o > 0; o >>= 1) s += __shfl_xor_sync(0xffffffffu, s, o);
    if (lane == 0) reds[wid] = s;
    __syncthreads();
    s = 0.f;
#pragma unroll
    for (int i = 0; i < 8; i++) s += reds[i];
    const float inv = 1.0f / s;

#pragma unroll
    for (int i = 0; i < 4; i++) {
        __half h0 = __float2half_rn(v[i].x * inv);
        __half h1 = __float2half_rn(v[i].y * inv);
        __half h2 = __float2half_rn(v[i].z * inv);
        __half h3 = __float2half_rn(v[i].w * inv);
        const long long off = rbase + i * 1024 + tid * 4;
        *(uint2*)&Ph[off] = make_uint2(packh2(h0, h1), packh2(h2, h3));
    }
}

// ---------------------------------------------------------------------------
extern "C" void kernel_launch(void* const* d_in, const int* in_sizes, int n_in,
                              void* d_out, int out_size)
{
    (void)in_sizes; (void)n_in; (void)out_size;
    const float* X  = (const float*)d_in[0];
    const float* Y  = (const float*)d_in[1];
    const float* Z  = (const float*)d_in[2];
    const float* Wk = (const float*)d_in[3];
    const float* Wv = (const float*)d_in[4];
    float* out = (float*)d_out;

    float *Kp, *Vp, *Sp;
    __half *Xh, *Kh, *Kl, *Vth, *Vtl, *Ph;
    cudaGetSymbolAddress((void**)&Kp,  g_K);
    cudaGetSymbolAddress((void**)&Vp,  g_V);
    cudaGetSymbolAddress((void**)&Sp,  g_S);
    cudaGetSymbolAddress((void**)&Xh,  g_Xh);
    cudaGetSymbolAddress((void**)&Kh,  g_Kh);
    cudaGetSymbolAddress((void**)&Kl,  g_Kl);
    cudaGetSymbolAddress((void**)&Vth, g_Vth);
    cudaGetSymbolAddress((void**)&Vtl, g_Vtl);
    cudaGetSymbolAddress((void**)&Ph,  g_Ph);

    cudaFuncSetAttribute(hmma_gemm_nt, cudaFuncAttributeMaxDynamicSharedMemorySize, SMEMSZ);

    const float rs = 0.0441941738241592f;  // 1/sqrt(512)

    // Projections (fp32 FFMA)
    sgemm_nt<<<dim3(512 / BN, 4096 / BM), 256>>>(Y, Wk, Kp, 512, 512);
    sgemm_nt<<<dim3(256 / BN, 4096 / BM), 256>>>(Z, Wv, Vp, 256, 512);

    // conversions
    tohalf_kernel<<<(SQB * DDK) / 1024, 256>>>(X, Xh);
    split2_kernel<<<(SKK * DDK) / 1024, 256>>>(Kp, Kh, Kl);
    vtsplit_kernel<<<dim3(SKK / 32, DVV / 32), 256>>>(Vp, Vth, Vtl);

    // S = X K^T * rs  (fp16 asymmetric 2-term: X exact-ish, K 2-digit)
    hmma_gemm_nt<<<dim3(SKK / 128, SQB / 128), 256, SMEMSZ>>>(
        Xh, Kh, Kl, Sp, DDK, SKK, rs);

    // softmax -> P fp16
    softmax_half_kernel<<<SQB, 256>>>(Sp, Ph);

    // out = P V  (fp16 asymmetric 2-term: P single, V 2-digit)
    hmma_gemm_nt<<<dim3(DVV / 128, SQB / 128), 256, SMEMSZ>>>(
        Ph, Vth, Vtl, out, SKK, DVV, 1.f);
}

// round 9
// speedup vs baseline: 4.3478x; 1.3188x over previous
#include <cuda_runtime.h>
#include <cuda_fp16.h>
#include <math.h>
#include <stdint.h>

#define SQB 16384
#define SKK 4096
#define DDK 512
#define DVV 256

// ---------------- scratch ----------------
__device__ __align__(256) float  g_K[SKK * DDK];
__device__ __align__(256) float  g_V[SKK * DVV];
__device__ __align__(256) float  g_S[(long long)SQB * SKK];
__device__ __align__(256) __half g_Xh[(long long)SQB * DDK];
__device__ __align__(256) __half g_Kh[SKK * DDK];
__device__ __align__(256) __half g_Vth[DVV * SKK];
__device__ __align__(256) __half g_Ph[(long long)SQB * SKK];

// ---------------- helpers ----------------
__device__ __forceinline__ uint32_t smem_u32(const void* p) {
    uint32_t a;
    asm("{ .reg .u64 t; cvta.to.shared.u64 t, %1; cvt.u32.u64 %0, t; }" : "=r"(a) : "l"(p));
    return a;
}
__device__ __forceinline__ void cp16(uint32_t s, const void* g) {
    asm volatile("cp.async.cg.shared.global [%0], [%1], 16;"
                 :: "r"(s), "l"(__cvta_generic_to_global(g)) : "memory");
}
#define CP_COMMIT() asm volatile("cp.async.commit_group;" ::: "memory")
#define CP_WAIT(n)  asm volatile("cp.async.wait_group %0;" :: "n"(n) : "memory")

#define LDSM4(r, a) \
    asm volatile("ldmatrix.sync.aligned.m8n8.x4.shared.b16 {%0,%1,%2,%3}, [%4];" \
                 : "=r"((r)[0]), "=r"((r)[1]), "=r"((r)[2]), "=r"((r)[3]) : "r"(a))

#define MMA_F16(d, a, b) \
    asm volatile("mma.sync.aligned.m16n8k16.row.col.f32.f16.f16.f32 " \
                 "{%0,%1,%2,%3}, {%4,%5,%6,%7}, {%8,%9}, {%0,%1,%2,%3};" \
                 : "+f"((d)[0]), "+f"((d)[1]), "+f"((d)[2]), "+f"((d)[3]) \
                 : "r"((a)[0]), "r"((a)[1]), "r"((a)[2]), "r"((a)[3]), \
                   "r"((b)[0]), "r"((b)[1]))

// ---------------- HMMA NT GEMM, single fp16 -------------------------------
// C[M,N] = A[M,K] * B[N,K]^T * scale
// CTA 128x128, 256 thr (8 warps, 64x32 each). K-chunk 32, 2 stages.
#define KC 32
#define ROWB 80                 // 64B data + 16B pad per smem row
#define PLANE (128 * ROWB)      // 10240 B
#define OFF_A  0
#define OFF_B  (1 * PLANE)
#define STAGE  (2 * PLANE)      // 20480 B
#define SMEMSZ (2 * STAGE)      // 40960 B

__device__ __forceinline__ void load_stage(
    uint32_t base, int tid, int kc0, int Kdim,
    const __half* __restrict__ A, const __half* __restrict__ B,
    long long m0, long long n0)
{
#pragma unroll
    for (int it = 0; it < 2; it++) {
        const int j = tid + it * 256;        // 512 jobs: 128 rows x 4 x 16B
        const int row = j >> 2;
        const int part = j & 3;
        const uint32_t off = (uint32_t)row * ROWB + part * 16;
        cp16(base + OFF_A + off, A + (m0 + row) * (long long)Kdim + kc0 + part * 8);
        cp16(base + OFF_B + off, B + (n0 + row) * (long long)Kdim + kc0 + part * 8);
    }
    CP_COMMIT();
}

__global__ __launch_bounds__(256)
void hmma_gemm_nt(const __half* __restrict__ A, const __half* __restrict__ B,
                  float* __restrict__ C, int Kdim, int ldc, float scale)
{
    extern __shared__ char sm[];
    const uint32_t sb = smem_u32(sm);

    const int tid  = threadIdx.x;
    const int lane = tid & 31;
    const int wid  = tid >> 5;
    const int wm   = wid & 1;    // 2 warps along M
    const int wn   = wid >> 1;   // 4 warps along N
    const long long m0 = (long long)blockIdx.y * 128;
    const long long n0 = (long long)blockIdx.x * 128;

    float acc[4][4][4];
#pragma unroll
    for (int i = 0; i < 4; i++)
#pragma unroll
        for (int j = 0; j < 4; j++)
#pragma unroll
            for (int k = 0; k < 4; k++) acc[i][j][k] = 0.f;

    const int NC = Kdim / KC;

    load_stage(sb,         tid, 0,  Kdim, A, B, m0, n0);
    load_stage(sb + STAGE, tid, KC, Kdim, A, B, m0, n0);

    const int g = lane >> 3;
    const int r = lane & 7;

    for (int c = 0; c < NC; c++) {
        const int st = c & 1;
        const uint32_t base = sb + st * STAGE;
        if (c + 2 < NC) { CP_WAIT(1); } else { CP_WAIT(0); }
        __syncthreads();

#pragma unroll
        for (int ks = 0; ks < 2; ks++) {
            uint32_t a_f[4][4], b_f[4][2];
#pragma unroll
            for (int mi = 0; mi < 4; mi++) {
                const uint32_t row = wm * 64 + mi * 16 + (g & 1) * 8 + r;
                const uint32_t cb  = ks * 32 + (g >> 1) * 16;
                LDSM4(a_f[mi], base + OFF_A + row * ROWB + cb);
            }
#pragma unroll
            for (int np = 0; np < 2; np++) {
                const uint32_t row = wn * 32 + np * 16 + (g >> 1) * 8 + r;
                const uint32_t cb  = ks * 32 + (g & 1) * 16;
                uint32_t t[4];
                LDSM4(t, base + OFF_B + row * ROWB + cb);
                b_f[np * 2][0] = t[0]; b_f[np * 2][1] = t[1];
                b_f[np * 2 + 1][0] = t[2]; b_f[np * 2 + 1][1] = t[3];
            }
#pragma unroll
            for (int mi = 0; mi < 4; mi++)
#pragma unroll
                for (int ni = 0; ni < 4; ni++)
                    MMA_F16(acc[mi][ni], a_f[mi], b_f[ni]);
        }
        __syncthreads();
        if (c + 2 < NC)
            load_stage(base, tid, (c + 2) * KC, Kdim, A, B, m0, n0);
    }

    // epilogue: fragment -> gmem (float2 stores)
#pragma unroll
    for (int mi = 0; mi < 4; mi++)
#pragma unroll
        for (int ni = 0; ni < 4; ni++) {
            const long long row = m0 + wm * 64 + mi * 16 + (lane >> 2);
            const long long col = n0 + wn * 32 + ni * 8 + 2 * (lane & 3);
            float2 v0 = make_float2(acc[mi][ni][0] * scale, acc[mi][ni][1] * scale);
            float2 v1 = make_float2(acc[mi][ni][2] * scale, acc[mi][ni][3] * scale);
            *(float2*)&C[row * ldc + col]       = v0;
            *(float2*)&C[(row + 8) * ldc + col] = v1;
        }
}

// ---------------- fp32 NT SGEMM for projections ----------------
#define BM 128
#define BN 128
#define BKK 8
#define PADW 132

__global__ __launch_bounds__(256, 2)
void sgemm_nt(const float* __restrict__ Ag, const float* __restrict__ Bg,
              float* __restrict__ Cg, int N, int K)
{
    __shared__ float As[2][BKK][PADW];
    __shared__ float Bs[2][BKK][PADW];

    const int tid = threadIdx.x;
    const int tx = tid & 15, ty = tid >> 4;
    const int row0 = blockIdx.y * BM, col0 = blockIdx.x * BN;
    const int aRow = row0 + (tid >> 1);
    const int aCol = (tid & 1) * 4;
    const int bRow = col0 + (tid >> 1);

    float acc[8][8];
#pragma unroll
    for (int i = 0; i < 8; i++)
#pragma unroll
        for (int j = 0; j < 8; j++) acc[i][j] = 0.f;

    const int nt = K / BKK;
    float4 ra = *(const float4*)&Ag[(long long)aRow * K + aCol];
    float4 rb = *(const float4*)&Bg[(long long)bRow * K + aCol];
    {
        const int m = tid >> 1;
        As[0][aCol + 0][m] = ra.x; As[0][aCol + 1][m] = ra.y;
        As[0][aCol + 2][m] = ra.z; As[0][aCol + 3][m] = ra.w;
        Bs[0][aCol + 0][m] = rb.x; Bs[0][aCol + 1][m] = rb.y;
        Bs[0][aCol + 2][m] = rb.z; Bs[0][aCol + 3][m] = rb.w;
    }
    __syncthreads();

    for (int t = 0; t < nt; t++) {
        const int buf = t & 1;
        if (t + 1 < nt) {
            const int k0 = (t + 1) * BKK;
            ra = *(const float4*)&Ag[(long long)aRow * K + k0 + aCol];
            rb = *(const float4*)&Bg[(long long)bRow * K + k0 + aCol];
        }
#pragma unroll
        for (int kk = 0; kk < BKK; kk++) {
            float4 a0 = *(const float4*)&As[buf][kk][ty * 4];
            float4 a1 = *(const float4*)&As[buf][kk][64 + ty * 4];
            float4 b0 = *(const float4*)&Bs[buf][kk][tx * 4];
            float4 b1 = *(const float4*)&Bs[buf][kk][64 + tx * 4];
            float av[8] = {a0.x, a0.y, a0.z, a0.w, a1.x, a1.y, a1.z, a1.w};
            float bv[8] = {b0.x, b0.y, b0.z, b0.w, b1.x, b1.y, b1.z, b1.w};
#pragma unroll
            for (int i = 0; i < 8; i++)
#pragma unroll
                for (int j = 0; j < 8; j++)
                    acc[i][j] += av[i] * bv[j];
        }
        if (t + 1 < nt) {
            const int nb = (t + 1) & 1;
            const int m = tid >> 1;
            As[nb][aCol + 0][m] = ra.x; As[nb][aCol + 1][m] = ra.y;
            As[nb][aCol + 2][m] = ra.z; As[nb][aCol + 3][m] = ra.w;
            Bs[nb][aCol + 0][m] = rb.x; Bs[nb][aCol + 1][m] = rb.y;
            Bs[nb][aCol + 2][m] = rb.z; Bs[nb][aCol + 3][m] = rb.w;
        }
        __syncthreads();
    }

#pragma unroll
    for (int i = 0; i < 8; i++) {
        const int r = row0 + ((i < 4) ? (ty * 4 + i) : (64 + ty * 4 + (i - 4)));
        float4 v0 = make_float4(acc[i][0], acc[i][1], acc[i][2], acc[i][3]);
        float4 v1 = make_float4(acc[i][4], acc[i][5], acc[i][6], acc[i][7]);
        *(float4*)&Cg[(long long)r * N + col0 + tx * 4]      = v0;
        *(float4*)&Cg[(long long)r * N + col0 + 64 + tx * 4] = v1;
    }
}

// ---------------- conversion kernels ----------------
__device__ __forceinline__ uint32_t packh2(__half a, __half b) {
    return (uint32_t)__half_as_ushort(a) | ((uint32_t)__half_as_ushort(b) << 16);
}

// fp32 -> fp16, 4 elems/thread
__global__ __launch_bounds__(256)
void tohalf_kernel(const float* __restrict__ in, __half* __restrict__ out)
{
    const long long i = (long long)blockIdx.x * 256 + threadIdx.x;
    float4 v = ((const float4*)in)[i];
    ((uint2*)out)[i] = make_uint2(packh2(__float2half_rn(v.x), __float2half_rn(v.y)),
                                  packh2(__float2half_rn(v.z), __float2half_rn(v.w)));
}

// V [4096,256] fp32 -> V^T [256,4096] fp16, 32x32 smem tile transpose
__global__ __launch_bounds__(256)
void vthalf_kernel(const float* __restrict__ V, __half* __restrict__ th)
{
    __shared__ float t[32][33];
    const int x = threadIdx.x & 31;
    const int y = threadIdx.x >> 5;
    const int k0 = blockIdx.x * 32;
    const int n0 = blockIdx.y * 32;
#pragma unroll
    for (int i = 0; i < 4; i++)
        t[y + i * 8][x] = V[(long long)(k0 + y + i * 8) * 256 + n0 + x];
    __syncthreads();
#pragma unroll
    for (int i = 0; i < 4; i++)
        th[(long long)(n0 + y + i * 8) * 4096 + k0 + x] =
            __float2half_rn(t[x][y + i * 8]);
}

// ---------------- softmax (fp32 in) -> P fp16 ----------------
__global__ __launch_bounds__(256)
void softmax_half_kernel(const float* __restrict__ S, __half* __restrict__ Ph)
{
    const long long rbase = (long long)blockIdx.x * 4096;
    const float* p = S + rbase;
    const int tid = threadIdx.x, wid = tid >> 5, lane = tid & 31;

    float4 v[4];
#pragma unroll
    for (int i = 0; i < 4; i++) v[i] = *(const float4*)&p[i * 1024 + tid * 4];

    float m = -INFINITY;
#pragma unroll
    for (int i = 0; i < 4; i++)
        m = fmaxf(m, fmaxf(fmaxf(v[i].x, v[i].y), fmaxf(v[i].z, v[i].w)));
#pragma unroll
    for (int o = 16; o > 0; o >>= 1) m = fmaxf(m, __shfl_xor_sync(0xffffffffu, m, o));

    __shared__ float redm[8], reds[8];
    if (lane == 0) redm[wid] = m;
    __syncthreads();
    m = redm[0];
#pragma unroll
    for (int i = 1; i < 8; i++) m = fmaxf(m, redm[i]);

    float s = 0.f;
#pragma unroll
    for (int i = 0; i < 4; i++) {
        v[i].x = __expf(v[i].x - m); v[i].y = __expf(v[i].y - m);
        v[i].z = __expf(v[i].z - m); v[i].w = __expf(v[i].w - m);
        s += v[i].x + v[i].y + v[i].z + v[i].w;
    }
#pragma unroll
    for (int o = 16; o > 0; o >>= 1) s += __shfl_xor_sync(0xffffffffu, s, o);
    if (lane == 0) reds[wid] = s;
    __syncthreads();
    s = 0.f;
#pragma unroll
    for (int i = 0; i < 8; i++) s += reds[i];
    const float inv = 1.0f / s;

#pragma unroll
    for (int i = 0; i < 4; i++) {
        __half h0 = __float2half_rn(v[i].x * inv);
        __half h1 = __float2half_rn(v[i].y * inv);
        __half h2 = __float2half_rn(v[i].z * inv);
        __half h3 = __float2half_rn(v[i].w * inv);
        const long long off = rbase + i * 1024 + tid * 4;
        *(uint2*)&Ph[off] = make_uint2(packh2(h0, h1), packh2(h2, h3));
    }
}

// ---------------------------------------------------------------------------
extern "C" void kernel_launch(void* const* d_in, const int* in_sizes, int n_in,
                              void* d_out, int out_size)
{
    (void)in_sizes; (void)n_in; (void)out_size;
    const float* X  = (const float*)d_in[0];
    const float* Y  = (const float*)d_in[1];
    const float* Z  = (const float*)d_in[2];
    const float* Wk = (const float*)d_in[3];
    const float* Wv = (const float*)d_in[4];
    float* out = (float*)d_out;

    float *Kp, *Vp, *Sp;
    __half *Xh, *Kh, *Vth, *Ph;
    cudaGetSymbolAddress((void**)&Kp,  g_K);
    cudaGetSymbolAddress((void**)&Vp,  g_V);
    cudaGetSymbolAddress((void**)&Sp,  g_S);
    cudaGetSymbolAddress((void**)&Xh,  g_Xh);
    cudaGetSymbolAddress((void**)&Kh,  g_Kh);
    cudaGetSymbolAddress((void**)&Vth, g_Vth);
    cudaGetSymbolAddress((void**)&Ph,  g_Ph);

    cudaFuncSetAttribute(hmma_gemm_nt, cudaFuncAttributeMaxDynamicSharedMemorySize, SMEMSZ);

    const float rs = 0.0441941738241592f;  // 1/sqrt(512)

    // Projections (fp32 FFMA)
    sgemm_nt<<<dim3(512 / BN, 4096 / BM), 256>>>(Y, Wk, Kp, 512, 512);
    sgemm_nt<<<dim3(256 / BN, 4096 / BM), 256>>>(Z, Wv, Vp, 256, 512);

    // conversions to fp16
    tohalf_kernel<<<(SQB * DDK) / 1024, 256>>>(X, Xh);
    tohalf_kernel<<<(SKK * DDK) / 1024, 256>>>(Kp, Kh);
    vthalf_kernel<<<dim3(SKK / 32, DVV / 32), 256>>>(Vp, Vth);

    // S = X K^T * rs  (single fp16)
    hmma_gemm_nt<<<dim3(SKK / 128, SQB / 128), 256, SMEMSZ>>>(
        Xh, Kh, Sp, DDK, SKK, rs);

    // softmax -> P fp16
    softmax_half_kernel<<<SQB, 256>>>(Sp, Ph);

    // out = P V  (single fp16)
    hmma_gemm_nt<<<dim3(DVV / 128, SQB / 128), 256, SMEMSZ>>>(
        Ph, Vth, out, SKK, DVV, 1.f);
}